// round 1
// baseline (speedup 1.0000x reference)
#include <cuda_runtime.h>

// PushingEnv: B independent 2-body contact sims, H=200 Euler steps.
//
// Exact algebraic restructuring (C=1, DT=0.01, K=100):
//   f*dt = -max(0, x1 + 1 - x2)          (K*DT = 1 exactly)
//   sum coords  s = x1+x2, sv = v1+v2:   sv_n = 0.99*sv, s_n = s + 0.01*sv_n
//       -> contact force cancels; closed form s_H = s0 + C_SUM*sv0
//   diff coords w = x1-x2:
//       a := -0.02*(w+1), q := 0.01*(v1-v2)
//       per step: r = min(a,0); q = 0.99*q + r; a = a - 0.02*q
//       (3 instructions: FMNMX on alu pipe + 2x FFMA-imm at rt=1 on fma pipe)
//   recover w = -50*a - 1; x1 = (s+w)/2; x2 = (s-w)/2; loss = (x2-goal)^2.

constexpr int H = 200;

// C_SUM = sum_{n=1..H} 0.01 * 0.99^n, evaluated at compile time in fp32.
constexpr float compute_c_sum() {
    float sv = 1.0f, s = 0.0f;
    for (int i = 0; i < H; ++i) {
        sv *= 0.99f;
        s += 0.01f * sv;
    }
    return s;
}
constexpr float C_SUM = compute_c_sum();

__global__ void __launch_bounds__(256) pushing_env_kernel(
    const float* __restrict__ x1_0,
    const float* __restrict__ v1_0,
    const float* __restrict__ x2_0,
    const float* __restrict__ v2_0,
    const float* __restrict__ goal,
    float* __restrict__ out,
    int n)
{
    int i = blockIdx.x * blockDim.x + threadIdx.x;
    if (i >= n) return;

    float x1 = x1_0[i];
    float v1 = v1_0[i];
    float x2 = x2_0[i];
    float v2 = v2_0[i];

    // difference-mode state
    float w = x1 - x2;
    float q = 0.01f * (v1 - v2);
    float a = fmaf(w, -0.02f, -0.02f);   // -0.02*(w+1)

    #pragma unroll
    for (int t = 0; t < H; ++t) {
        float r = fminf(a, 0.0f);        // -0.02 * max(0, w+1)
        q = fmaf(q, 0.99f, r);           // q_n = 0.99*q - 0.02*g
        a = fmaf(q, -0.02f, a);          // a_n = -0.02*(w_n + 1)
    }
    w = fmaf(a, -50.0f, -1.0f);          // w_H

    // sum-mode closed form
    float s = fmaf(v1 + v2, C_SUM, x1 + x2);

    float xf1 = 0.5f * (s + w);
    float xf2 = 0.5f * (s - w);
    float d = xf2 - goal[i];

    out[i]         = d * d;   // loss
    out[n + i]     = xf1;     // x1
    out[2 * n + i] = xf2;     // x2
}

extern "C" void kernel_launch(void* const* d_in, const int* in_sizes, int n_in,
                              void* d_out, int out_size)
{
    // inputs: [0]=u_seq(H) [1]=x1_0 [2]=v1_0 [3]=x2_0 [4]=v2_0 [5]=goal [6]=gtype
    const float* x1_0 = (const float*)d_in[1];
    const float* v1_0 = (const float*)d_in[2];
    const float* x2_0 = (const float*)d_in[3];
    const float* v2_0 = (const float*)d_in[4];
    const float* goal = (const float*)d_in[5];
    int n = in_sizes[1];

    int threads = 256;
    int blocks = (n + threads - 1) / threads;
    pushing_env_kernel<<<blocks, threads>>>(x1_0, v1_0, x2_0, v2_0, goal,
                                            (float*)d_out, n);
}

// round 3
// speedup vs baseline: 1.0338x; 1.0338x over previous
#include <cuda_runtime.h>
#include <cstdint>

// PushingEnv: B independent 2-body contact sims, H=200 Euler steps.
//
// Algebraic restructuring (C=1, DT=0.01, K=100, K*DT = 1 exactly):
//   sum coords  s = x1+x2, sv = v1+v2: contact force cancels ->
//       closed form s_H = s0 + C_SUM*sv0   (C_SUM = sum 0.01*0.99^n)
//   diff coords w = x1-x2:
//       a := -0.02*(w+1), q := 0.01*(v1-v2)
//       per step: r = min(a,0); q = 0.99*q + r; a = a - 0.02*q
//   recover w = -50*a - 1; x1=(s+w)/2; x2=(s-w)/2; loss=(x2-goal)^2.
//
// R3 (= R2 resubmit; infra failure last round): two envs per thread, packed
// f32x2 FFMA (Blackwell FFMA2, PTX fma.rn.f32x2) for the two FMAs, scalar
// FMNMX per half for the min. 4 core issues/step/warp covering 64 envs.

constexpr int H = 200;

constexpr float compute_c_sum() {
    float sv = 1.0f, s = 0.0f;
    for (int i = 0; i < H; ++i) { sv *= 0.99f; s += 0.01f * sv; }
    return s;
}
constexpr float C_SUM = compute_c_sum();

__device__ __forceinline__ uint64_t pack2(float lo, float hi) {
    uint64_t d;
    asm("mov.b64 %0, {%1, %2};" : "=l"(d) : "f"(lo), "f"(hi));
    return d;
}
__device__ __forceinline__ void unpack2(uint64_t d, float& lo, float& hi) {
    asm("mov.b64 {%0, %1}, %2;" : "=f"(lo), "=f"(hi) : "l"(d));
}
__device__ __forceinline__ uint64_t ffma2(uint64_t a, uint64_t b, uint64_t c) {
    uint64_t d;
    asm("fma.rn.f32x2 %0, %1, %2, %3;" : "=l"(d) : "l"(a), "l"(b), "l"(c));
    return d;
}

__global__ void __launch_bounds__(128) pushing_env_kernel(
    const float* __restrict__ x1_0,
    const float* __restrict__ v1_0,
    const float* __restrict__ x2_0,
    const float* __restrict__ v2_0,
    const float* __restrict__ goal,
    float* __restrict__ out,
    int n)
{
    int i = blockIdx.x * blockDim.x + threadIdx.x;
    int j = 2 * i;
    if (j >= n) return;

    if (j + 1 < n) {
        // vector loads: two consecutive envs
        float2 x1 = *(const float2*)(x1_0 + j);
        float2 v1 = *(const float2*)(v1_0 + j);
        float2 x2 = *(const float2*)(x2_0 + j);
        float2 v2 = *(const float2*)(v2_0 + j);
        float2 gl = *(const float2*)(goal + j);

        // difference-mode packed state
        float a0 = fmaf(x1.x - x2.x, -0.02f, -0.02f);
        float a1 = fmaf(x1.y - x2.y, -0.02f, -0.02f);
        uint64_t Q = pack2(0.01f * (v1.x - v2.x), 0.01f * (v1.y - v2.y));
        uint64_t A = pack2(a0, a1);

        const uint64_t C99  = pack2(0.99f, 0.99f);
        const uint64_t CM02 = pack2(-0.02f, -0.02f);

        #pragma unroll
        for (int t = 0; t < H; ++t) {
            float alo, ahi;
            unpack2(A, alo, ahi);
            uint64_t R = pack2(fminf(alo, 0.0f), fminf(ahi, 0.0f));
            Q = ffma2(Q, C99, R);        // q = 0.99*q + min(a,0)
            A = ffma2(Q, CM02, A);       // a = a - 0.02*q
        }

        float af0, af1;
        unpack2(A, af0, af1);
        float w0 = fmaf(af0, -50.0f, -1.0f);
        float w1 = fmaf(af1, -50.0f, -1.0f);

        // sum-mode closed form
        float s0 = fmaf(v1.x + v2.x, C_SUM, x1.x + x2.x);
        float s1 = fmaf(v1.y + v2.y, C_SUM, x1.y + x2.y);

        float2 xf1 = make_float2(0.5f * (s0 + w0), 0.5f * (s1 + w1));
        float2 xf2 = make_float2(0.5f * (s0 - w0), 0.5f * (s1 - w1));
        float d0 = xf2.x - gl.x;
        float d1 = xf2.y - gl.y;

        *(float2*)(out + j)         = make_float2(d0 * d0, d1 * d1);
        *(float2*)(out + n + j)     = xf1;
        *(float2*)(out + 2 * n + j) = xf2;
    } else {
        // scalar tail (n odd; not hit for B=262144)
        float x1 = x1_0[j], v1 = v1_0[j], x2 = x2_0[j], v2 = v2_0[j];
        float q = 0.01f * (v1 - v2);
        float a = fmaf(x1 - x2, -0.02f, -0.02f);
        #pragma unroll
        for (int t = 0; t < H; ++t) {
            float r = fminf(a, 0.0f);
            q = fmaf(q, 0.99f, r);
            a = fmaf(q, -0.02f, a);
        }
        float w = fmaf(a, -50.0f, -1.0f);
        float s = fmaf(v1 + v2, C_SUM, x1 + x2);
        float xf1 = 0.5f * (s + w);
        float xf2 = 0.5f * (s - w);
        float d = xf2 - goal[j];
        out[j] = d * d;
        out[n + j] = xf1;
        out[2 * n + j] = xf2;
    }
}

extern "C" void kernel_launch(void* const* d_in, const int* in_sizes, int n_in,
                              void* d_out, int out_size)
{
    // inputs: [0]=u_seq(H) [1]=x1_0 [2]=v1_0 [3]=x2_0 [4]=v2_0 [5]=goal [6]=gtype
    const float* x1_0 = (const float*)d_in[1];
    const float* v1_0 = (const float*)d_in[2];
    const float* x2_0 = (const float*)d_in[3];
    const float* v2_0 = (const float*)d_in[4];
    const float* goal = (const float*)d_in[5];
    int n = in_sizes[1];

    int threads = 128;
    int pairs = (n + 1) / 2;
    int blocks = (pairs + threads - 1) / threads;
    pushing_env_kernel<<<blocks, threads>>>(x1_0, v1_0, x2_0, v2_0, goal,
                                            (float*)d_out, n);
}